// round 10
// baseline (speedup 1.0000x reference)
#include <cuda_runtime.h>
#include <cuda_bf16.h>
#include <cstdint>

// InterAgg (FRAUDRE inter-relation aggregation), GB300 sm_103a.
//
// out[n] = [ self | relu(self) | sum_r relu(mean_j feat[nidx_r[n,j]]) * softmax(alpha)[64:,r] ]
// (softmax rows sum to 1 => aggregated first half == relu(self) exactly)
//
// R9: 256-bit gathers (ld.global.nc.v8.b32, required by ptxas for L2 evict
// hints on sm_103a) + deterministic L2 residency: rows < KEEP_ROWS load with
// evict_last (~102MB pinned across graph replays), the rest evict_first.
// Warp layout: group g=lane>>3 covers row j+g, sublane sl=lane&7 owns dims
// 8sl..8sl+7; one warp instruction gathers 4 rows (1024B coalesced).

#define NB 8192
#define DEG 32
#define KEEP_ROWS 400000   // 400000 rows * 256B = 102.4 MB resident set

__device__ __forceinline__ void ldg_evict8(const float* p, int keep, float* v) {
    uint32_t r0, r1, r2, r3, r4, r5, r6, r7;
    asm volatile("{\n\t"
        ".reg .pred pk;\n\t"
        "setp.ne.u32 pk, %9, 0;\n\t"
        "@pk  ld.global.nc.L2::evict_last.v8.b32  {%0,%1,%2,%3,%4,%5,%6,%7}, [%8];\n\t"
        "@!pk ld.global.nc.L2::evict_first.v8.b32 {%0,%1,%2,%3,%4,%5,%6,%7}, [%8];\n\t"
        "}"
        : "=r"(r0), "=r"(r1), "=r"(r2), "=r"(r3),
          "=r"(r4), "=r"(r5), "=r"(r6), "=r"(r7)
        : "l"(p), "r"(keep));
    v[0] = __uint_as_float(r0); v[1] = __uint_as_float(r1);
    v[2] = __uint_as_float(r2); v[3] = __uint_as_float(r3);
    v[4] = __uint_as_float(r4); v[5] = __uint_as_float(r5);
    v[6] = __uint_as_float(r6); v[7] = __uint_as_float(r7);
}

__device__ __forceinline__ void softmax3(float& a, float& b, float& c) {
    float m = fmaxf(a, fmaxf(b, c));
    float e0 = __expf(a - m);
    float e1 = __expf(b - m);
    float e2 = __expf(c - m);
    float inv = __frcp_rn(e0 + e1 + e2);
    a = e0 * inv; b = e1 * inv; c = e2 * inv;
}

__global__ __launch_bounds__(256, 3)
void interagg_kernel(const float* __restrict__ feat,    // (NUM_NODES, 64)
                     const float* __restrict__ alpha,   // (128, 3)
                     const int*   __restrict__ nodes,   // (NB,)
                     const int*   __restrict__ n1,      // (NB, DEG)
                     const int*   __restrict__ n2,
                     const int*   __restrict__ n3,
                     float*       __restrict__ out)     // (NB, 192)
{
    const int w    = (blockIdx.x * blockDim.x + threadIdx.x) >> 5;
    const int lane = threadIdx.x & 31;
    if (w >= NB) return;

    const int g  = lane >> 3;   // row-group 0..3
    const int sl = lane & 7;    // owns dims 8sl..8sl+7
    const int fo = sl * 8;      // float offset within a feature row

    // --- index loads (coalesced; lane j owns neighbor j) ---
    const int node = __ldg(&nodes[w]);
    const int base = w * DEG + lane;
    const int i1 = __ldg(&n1[base]);
    const int i2 = __ldg(&n2[base]);
    const int i3 = __ldg(&n3[base]);

    // --- self row (replicated across groups; L2 dedups the broadcast) ---
    float s[8];
    ldg_evict8(feat + (size_t)node * 64 + fo, node < KEEP_ROWS, s);

    float a1[8] = {0,0,0,0,0,0,0,0};
    float a2[8] = {0,0,0,0,0,0,0,0};
    float a3[8] = {0,0,0,0,0,0,0,0};

    // --- gathers: one v8 warp instruction = 4 neighbor rows (1024B) ---
#pragma unroll
    for (int i = 0; i < DEG / 4; i++) {
        const int src = 4 * i + g;
        const int x1 = __shfl_sync(0xffffffffu, i1, src);
        const int x2 = __shfl_sync(0xffffffffu, i2, src);
        const int x3 = __shfl_sync(0xffffffffu, i3, src);

        float v1[8], v2[8], v3[8];
        ldg_evict8(feat + (size_t)x1 * 64 + fo, x1 < KEEP_ROWS, v1);
        ldg_evict8(feat + (size_t)x2 * 64 + fo, x2 < KEEP_ROWS, v2);
        ldg_evict8(feat + (size_t)x3 * 64 + fo, x3 < KEEP_ROWS, v3);

#pragma unroll
        for (int k = 0; k < 8; k++) {
            a1[k] += v1[k];
            a2[k] += v2[k];
            a3[k] += v3[k];
        }
    }

    // --- fold the 4 row-groups (lanes l, l^8, l^16, l^24 share dims) ---
#pragma unroll
    for (int k = 0; k < 8; k++) {
        a1[k] += __shfl_xor_sync(0xffffffffu, a1[k], 8);
        a2[k] += __shfl_xor_sync(0xffffffffu, a2[k], 8);
        a3[k] += __shfl_xor_sync(0xffffffffu, a3[k], 8);
        a1[k] += __shfl_xor_sync(0xffffffffu, a1[k], 16);
        a2[k] += __shfl_xor_sync(0xffffffffu, a2[k], 16);
        a3[k] += __shfl_xor_sync(0xffffffffu, a3[k], 16);
    }

    // --- softmax weights for agg dims 64+8sl .. 64+8sl+7: 24 floats ---
    // alpha row r starts at float 3r; rows 64+8sl.. => floats 192+24sl..+23
    float wv[24];
    {
        const float4* ap = reinterpret_cast<const float4*>(alpha + 192 + 24 * sl);
#pragma unroll
        for (int q = 0; q < 6; q++) {
            float4 t = __ldg(&ap[q]);
            wv[4 * q + 0] = t.x; wv[4 * q + 1] = t.y;
            wv[4 * q + 2] = t.z; wv[4 * q + 3] = t.w;
        }
    }
    float o[8];
    const float inv = 1.0f / (float)DEG;
#pragma unroll
    for (int k = 0; k < 8; k++) {
        float w0 = wv[3 * k + 0], w1 = wv[3 * k + 1], w2 = wv[3 * k + 2];
        softmax3(w0, w1, w2);
        const float g1 = fmaxf(a1[k] * inv, 0.f);
        const float g2 = fmaxf(a2[k] * inv, 0.f);
        const float g3 = fmaxf(a3[k] * inv, 0.f);
        o[k] = g1 * w0 + g2 * w1 + g3 * w2;
    }

    // --- write 192 floats: [self | relu(self) | weighted agg] ---
    float4* ob = reinterpret_cast<float4*>(out + (size_t)w * 192);
    if (g == 0) {
        ob[2 * sl + 0] = make_float4(s[0], s[1], s[2], s[3]);
        ob[2 * sl + 1] = make_float4(s[4], s[5], s[6], s[7]);
    } else if (g == 1) {
        ob[16 + 2 * sl + 0] = make_float4(fmaxf(s[0], 0.f), fmaxf(s[1], 0.f),
                                          fmaxf(s[2], 0.f), fmaxf(s[3], 0.f));
        ob[16 + 2 * sl + 1] = make_float4(fmaxf(s[4], 0.f), fmaxf(s[5], 0.f),
                                          fmaxf(s[6], 0.f), fmaxf(s[7], 0.f));
    } else if (g == 2) {
        ob[32 + 2 * sl + 0] = make_float4(o[0], o[1], o[2], o[3]);
        ob[32 + 2 * sl + 1] = make_float4(o[4], o[5], o[6], o[7]);
    }
}

extern "C" void kernel_launch(void* const* d_in, const int* in_sizes, int n_in,
                              void* d_out, int out_size) {
    const float* feat  = (const float*)d_in[0];
    const float* alpha = (const float*)d_in[1];
    const int*   nodes = (const int*)d_in[2];
    const int*   n1    = (const int*)d_in[3];
    const int*   n2    = (const int*)d_in[4];
    const int*   n3    = (const int*)d_in[5];
    float*       out   = (float*)d_out;

    const int threads = 256;   // 8 warps = 8 nodes / block
    const int blocks  = (NB * 32 + threads - 1) / threads;  // 1024
    interagg_kernel<<<blocks, threads>>>(feat, alpha, nodes, n1, n2, n3, out);
}